// round 12
// baseline (speedup 1.0000x reference)
#include <cuda_runtime.h>
#include <cuda_bf16.h>
#include <cstdint>
#include <math.h>

// Problem constants
#define B_    4
#define SQ_   1024
#define SKV_  4096
#define DQ_   1024
#define DKV_  768
#define H_    16
#define DH_   64
#define DOUT_ 256

#define SWZ(o) ((o) ^ (((o) >> 3) & 0x70))

// ---------------------------------------------------------------------------
// Scratch
// ---------------------------------------------------------------------------
#define AL16 __align__(16)
__device__ AL16 __nv_bfloat16 g_sqh[(size_t)B_ * SQ_  * DQ_ ], g_sql[(size_t)B_ * SQ_  * DQ_ ];
__device__ AL16 __nv_bfloat16 g_skh[(size_t)B_ * SKV_ * DKV_], g_skl[(size_t)B_ * SKV_ * DKV_];
__device__ AL16 __nv_bfloat16 g_svh[(size_t)B_ * SKV_ * DKV_], g_svl[(size_t)B_ * SKV_ * DKV_];
__device__ AL16 __nv_bfloat16 g_wqh[DQ_ * DQ_ ],  g_wql[DQ_ * DQ_ ];
__device__ AL16 __nv_bfloat16 g_wkh[DQ_ * DKV_],  g_wkl[DQ_ * DKV_];
__device__ AL16 __nv_bfloat16 g_wvh[DQ_ * DKV_],  g_wvl[DQ_ * DKV_];
__device__ AL16 __nv_bfloat16 g_woh[DOUT_ * DQ_], g_wol[DOUT_ * DQ_];
__device__ AL16 __nv_bfloat16 g_qh [(size_t)B_ * SQ_  * DQ_], g_ql [(size_t)B_ * SQ_  * DQ_];
__device__ AL16 __nv_bfloat16 g_kh [(size_t)B_ * SKV_ * DQ_], g_kl [(size_t)B_ * SKV_ * DQ_];
__device__ AL16 __nv_bfloat16 g_vh [(size_t)B_ * SKV_ * DQ_], g_vl [(size_t)B_ * SKV_ * DQ_];
__device__ AL16 __nv_bfloat16 g_vth[(size_t)B_ * DQ_ * SKV_], g_vtl[(size_t)B_ * DQ_ * SKV_];
__device__ AL16 __nv_bfloat16 g_ath[(size_t)B_ * SQ_ * DQ_], g_atl[(size_t)B_ * SQ_ * DQ_];
__device__ AL16 unsigned char g_maskT[(size_t)B_ * SQ_ * SKV_];
__device__ int g_mask_flag;

// ---------------------------------------------------------------------------
// Mask dtype probe
// ---------------------------------------------------------------------------
__global__ void probe_mask_kernel(const unsigned int* __restrict__ m)
{
    if (blockIdx.x != 0 || threadIdx.x != 0) return;
    int is_i32 = 1, is_f32 = 1;
    for (int i = 0; i < 4096; i++) {
        unsigned v = m[i];
        if (v > 1u) is_i32 = 0;
        if (v != 0u && v != 0x3F800000u) is_f32 = 0;
    }
    g_mask_flag = is_i32 ? 1 : (is_f32 ? 2 : 0);
}

__device__ __forceinline__ bool read_mask(const void* m, long i, int flag)
{
    if (flag == 1) return ((const int*)m)[i] != 0;
    if (flag == 2) return ((const float*)m)[i] != 0.0f;
    return ((const unsigned char*)m)[i] != 0;
}

// ---------------------------------------------------------------------------
// Mask transpose: mask[b][kv][q] (any dtype) -> u8 maskT[b][q][kv]
// ---------------------------------------------------------------------------
__global__ __launch_bounds__(256)
void transpose_mask_kernel(const void* __restrict__ mask,
                           unsigned char* __restrict__ maskT)
{
    __shared__ unsigned char t[32][33];
    const int b   = blockIdx.z;
    const int kv0 = blockIdx.x * 32, q0 = blockIdx.y * 32;
    const int x = threadIdx.x, y = threadIdx.y;      // 32 x 8
    const int flag = g_mask_flag;
#pragma unroll
    for (int i = y; i < 32; i += 8)
        t[i][x] = read_mask(mask, ((long)b * SKV_ + kv0 + i) * SQ_ + q0 + x, flag) ? 1 : 0;
    __syncthreads();
#pragma unroll
    for (int i = y; i < 32; i += 8)
        maskT[((long)b * SQ_ + q0 + i) * SKV_ + kv0 + x] = t[x][i];
}

// ---------------------------------------------------------------------------
// Primitives
// ---------------------------------------------------------------------------
__device__ __forceinline__ uint32_t smem_to_u32(const void* p) {
    uint32_t a;
    asm("{ .reg .u64 t; cvta.to.shared.u64 t, %1; cvt.u32.u64 %0, t; }"
        : "=r"(a) : "l"(p));
    return a;
}

__device__ __forceinline__ void ldm_x4(uint32_t addr, uint32_t* r) {
    asm volatile("ldmatrix.sync.aligned.m8n8.x4.shared.b16 {%0,%1,%2,%3}, [%4];"
                 : "=r"(r[0]), "=r"(r[1]), "=r"(r[2]), "=r"(r[3]) : "r"(addr));
}

__device__ __forceinline__ void mma_bf16(float* d, const uint32_t* a,
                                         uint32_t b0, uint32_t b1) {
    asm volatile(
        "mma.sync.aligned.m16n8k16.row.col.f32.bf16.bf16.f32 "
        "{%0,%1,%2,%3}, {%4,%5,%6,%7}, {%8,%9}, {%0,%1,%2,%3};"
        : "+f"(d[0]), "+f"(d[1]), "+f"(d[2]), "+f"(d[3])
        : "r"(a[0]), "r"(a[1]), "r"(a[2]), "r"(a[3]), "r"(b0), "r"(b1));
}

__device__ __forceinline__ uint32_t pk2(__nv_bfloat16 a, __nv_bfloat16 b)
{
    return (uint32_t)__bfloat16_as_ushort(a) | ((uint32_t)__bfloat16_as_ushort(b) << 16);
}

// cp.async a ROWSx64-bf16 tile (rows of 128B) into SW128 swizzled smem
template<int ROWS>
__device__ __forceinline__ void cpa_tile(uint32_t dst, const __nv_bfloat16* src,
                                         int ld, int tid)
{
#pragma unroll
    for (int i = 0; i < ROWS / 32; i++) {
        int f = tid + i * 256;
        int r = f >> 3, c = f & 7;
        uint32_t d = dst + SWZ((unsigned)(r * 128 + c * 16));
        const void* s = src + (long)r * ld + c * 8;
        asm volatile("cp.async.cg.shared.global [%0], [%1], 16;" :: "r"(d), "l"(s));
    }
}

// ---------------------------------------------------------------------------
// fp32 -> bf16 hi/lo split
// ---------------------------------------------------------------------------
__global__ __launch_bounds__(256)
void split_kernel(const float* __restrict__ src,
                  __nv_bfloat16* __restrict__ h, __nv_bfloat16* __restrict__ l)
{
    long i = ((long)blockIdx.x * 256 + threadIdx.x) * 4;
    float4 v = *(const float4*)(src + i);
    __nv_bfloat16 h0 = __float2bfloat16(v.x), h1 = __float2bfloat16(v.y);
    __nv_bfloat16 h2 = __float2bfloat16(v.z), h3 = __float2bfloat16(v.w);
    *(uint2*)(h + i) = make_uint2(pk2(h0, h1), pk2(h2, h3));
    *(uint2*)(l + i) = make_uint2(
        pk2(__float2bfloat16(v.x - __bfloat162float(h0)),
            __float2bfloat16(v.y - __bfloat162float(h1))),
        pk2(__float2bfloat16(v.z - __bfloat162float(h2)),
            __float2bfloat16(v.w - __bfloat162float(h3))));
}

// ---------------------------------------------------------------------------
// bf16 hi/lo GEMM via HMMA (projections + Wo).  D[128,64] = A[128,K] @ B[64,K]^T
// MODE 0: +bias, write bf16 h/l.  MODE 3: +bias, write fp32.
// ---------------------------------------------------------------------------
template<int MODE>
__global__ void __launch_bounds__(256, 2)
hgemm_kernel(const __nv_bfloat16* __restrict__ Ah, const __nv_bfloat16* __restrict__ Al, int lda,
             const __nv_bfloat16* __restrict__ Bh, const __nv_bfloat16* __restrict__ Bl, int ldb,
             const float* __restrict__ bias,
             void* __restrict__ C0, void* __restrict__ C1, int ldc, int Kdim)
{
    extern __shared__ char smem[];
    constexpr int NT = 64;
    constexpr int NF = NT / 16;
    constexpr unsigned ABY = 128 * 128;
    constexpr unsigned BBY = NT * 128;
    constexpr unsigned BUFSZ = 2 * ABY + 2 * BBY;

    const uint32_t sbase = smem_to_u32(smem);
    const int tid = threadIdx.x;
    const int wid = tid >> 5, lid = tid & 31;
    const int wm = wid & 3, wn = wid >> 2;
    const int m0 = blockIdx.y * 128, n0 = blockIdx.x * NT;

    const __nv_bfloat16* Aph = Ah + (long)m0 * lda;
    const __nv_bfloat16* Apl = Al + (long)m0 * lda;
    const __nv_bfloat16* Bph = Bh + (long)n0 * ldb;
    const __nv_bfloat16* Bpl = Bl + (long)n0 * ldb;
    const int LDA = lda, LDB = ldb, LDC = ldc;
    long co = (long)m0 * ldc + n0;

    float dc[2 * NF][4];
#pragma unroll
    for (int i = 0; i < 2 * NF; i++)
#pragma unroll
        for (int j = 0; j < 4; j++) dc[i][j] = 0.0f;

    const int ns = Kdim >> 6;

    auto issue = [&](int s) {
        uint32_t base = sbase + (unsigned)(s & 1) * BUFSZ;
        cpa_tile<128>(base,       Aph + (long)s * 64, LDA, tid);
        cpa_tile<128>(base + ABY, Apl + (long)s * 64, LDA, tid);
        cpa_tile<NT>(base + 2 * ABY,       Bph + (long)s * 64, LDB, tid);
        cpa_tile<NT>(base + 2 * ABY + BBY, Bpl + (long)s * 64, LDB, tid);
        asm volatile("cp.async.commit_group;" ::: "memory");
    };

    auto compute = [&](int buf) {
        const uint32_t sA  = sbase + (unsigned)buf * BUFSZ;
        const uint32_t sAl = sA + ABY;
        const uint32_t sB  = sA + 2 * ABY;
        const uint32_t sBl = sB + BBY;
        const int lr = lid & 15, hsel = (lid >> 4) << 4;
#pragma unroll
        for (int ks = 0; ks < 4; ks++) {
            const int kb = ks * 32 + hsel;
            uint32_t aH[2][4], aL[2][4];
#pragma unroll
            for (int i = 0; i < 2; i++) {
                unsigned off = SWZ((unsigned)((wm * 32 + i * 16 + lr) * 128 + kb));
                ldm_x4(sA + off, aH[i]);
                ldm_x4(sAl + off, aL[i]);
            }
#pragma unroll
            for (int jj = 0; jj < NF / 2; jj++) {
                unsigned off = SWZ((unsigned)((wn * (NT / 2) + jj * 16 + lr) * 128 + kb));
                uint32_t bH[4], bL[4];
                ldm_x4(sB + off, bH);
                ldm_x4(sBl + off, bL);
#pragma unroll
                for (int i = 0; i < 2; i++) {
#pragma unroll
                    for (int t = 0; t < 2; t++) {
                        float* d = dc[i * NF + jj * 2 + t];
                        mma_bf16(d, aH[i], bH[t], bH[t + 2]);
                        mma_bf16(d, aH[i], bL[t], bL[t + 2]);
                        mma_bf16(d, aL[i], bH[t], bH[t + 2]);
                    }
                }
            }
        }
    };

    issue(0);
    for (int s = 0; s < ns; s++) {
        if (s + 1 < ns) {
            issue(s + 1);
            asm volatile("cp.async.wait_group 1;" ::: "memory");
        } else {
            asm volatile("cp.async.wait_group 0;" ::: "memory");
        }
        __syncthreads();
        compute(s & 1);
        __syncthreads();
    }

#pragma unroll
    for (int i = 0; i < 2; i++) {
#pragma unroll
        for (int f = 0; f < NF; f++) {
            const float* d = dc[i * NF + f];
            int rl = wm * 32 + i * 16 + (lid >> 2);
            int cl = wn * (NT / 2) + f * 8 + ((lid & 3) << 1);
            float2 bb = *(const float2*)(bias + n0 + cl);
            float v0 = d[0] + bb.x, v1 = d[1] + bb.y;
            float v2 = d[2] + bb.x, v3 = d[3] + bb.y;
            if (MODE == 0) {
                __nv_bfloat16 h0 = __float2bfloat16(v0), h1 = __float2bfloat16(v1);
                __nv_bfloat16 h2 = __float2bfloat16(v2), h3 = __float2bfloat16(v3);
                __nv_bfloat16* ch = (__nv_bfloat16*)C0 + co;
                __nv_bfloat16* cll = (__nv_bfloat16*)C1 + co;
                *(uint32_t*)(ch + (long)rl * LDC + cl)       = pk2(h0, h1);
                *(uint32_t*)(ch + (long)(rl + 8) * LDC + cl) = pk2(h2, h3);
                *(uint32_t*)(cll + (long)rl * LDC + cl) =
                    pk2(__float2bfloat16(v0 - __bfloat162float(h0)),
                        __float2bfloat16(v1 - __bfloat162float(h1)));
                *(uint32_t*)(cll + (long)(rl + 8) * LDC + cl) =
                    pk2(__float2bfloat16(v2 - __bfloat162float(h2)),
                        __float2bfloat16(v3 - __bfloat162float(h3)));
            } else {
                float* cp = (float*)C0 + co;
                *(float2*)(cp + (long)rl * LDC + cl)       = make_float2(v0, v1);
                *(float2*)(cp + (long)(rl + 8) * LDC + cl) = make_float2(v2, v3);
            }
        }
    }
}

// ---------------------------------------------------------------------------
// Fused attention: scores + online softmax stats + normalized-Wt write + PV.
// Grid (SQ/128, B*H); per CTA: q-tile of 128, full kv sweep twice.
// Smem: Q h/l 32KB + 2 stages x (K h/l 16K + V h/l 16K + mask 8K) = 112KB.
// ---------------------------------------------------------------------------
#define FQ_H 0u
#define FQ_L 16384u
#define FST0 32768u
#define FSTRIDE 40960u
#define FK_H 0u
#define FK_L 8192u
#define FV_H 16384u
#define FV_L 24576u
#define FMK  32768u
#define FSMEM 114688

__global__ void __launch_bounds__(256, 2)
fused_attn_kernel(const __nv_bfloat16* __restrict__ qh, const __nv_bfloat16* __restrict__ ql,
                  const __nv_bfloat16* __restrict__ kh, const __nv_bfloat16* __restrict__ kl,
                  const __nv_bfloat16* __restrict__ vth, const __nv_bfloat16* __restrict__ vtl,
                  const unsigned char* __restrict__ maskT,
                  float* __restrict__ Wt,
                  __nv_bfloat16* __restrict__ ath, __nv_bfloat16* __restrict__ atl)
{
    extern __shared__ char smem[];
    const uint32_t sbase = smem_to_u32(smem);
    const int tid = threadIdx.x, wid = tid >> 5, lid = tid & 31;
    const int m0 = blockIdx.x * 128;
    const int z  = blockIdx.y;
    const int b = z >> 4, h = z & 15;

    const __nv_bfloat16* qph = qh + ((long)b * SQ_ + m0) * DQ_ + h * DH_;
    const __nv_bfloat16* qpl = ql + ((long)b * SQ_ + m0) * DQ_ + h * DH_;
    const __nv_bfloat16* kph = kh + (long)b * SKV_ * DQ_ + h * DH_;
    const __nv_bfloat16* kpl = kl + (long)b * SKV_ * DQ_ + h * DH_;
    const __nv_bfloat16* vph = vth + (long)(b * DQ_ + h * DH_) * SKV_;
    const __nv_bfloat16* vpl = vtl + (long)(b * DQ_ + h * DH_) * SKV_;
    const unsigned char* mp  = maskT + ((long)b * SQ_ + m0) * SKV_;
    float* wtp = Wt + ((long)z * SQ_ + m0) * SKV_;

    const int lr = lid & 15, hsel = (lid >> 4) << 4;
    const int r0 = wid * 16 + (lid >> 2);

    // Q tile -> smem (one group)
    cpa_tile<128>(sbase + FQ_H, qph, DQ_, tid);
    cpa_tile<128>(sbase + FQ_L, qpl, DQ_, tid);
    asm volatile("cp.async.commit_group;" ::: "memory");

    auto issue = [&](int s, bool withV) {
        uint32_t base = sbase + FST0 + (unsigned)(s & 1) * FSTRIDE;
        cpa_tile<64>(base + FK_H, kph + (long)s * 64 * DQ_, DQ_, tid);
        cpa_tile<64>(base + FK_L, kpl + (long)s * 64 * DQ_, DQ_, tid);
        if (withV) {
            cpa_tile<64>(base + FV_H, vph + s * 64, SKV_, tid);
            cpa_tile<64>(base + FV_L, vpl + s * 64, SKV_, tid);
        }
        const unsigned char* ms = mp + s * 64;
#pragma unroll
        for (int i = 0; i < 2; i++) {
            int f = tid + i * 256;
            int r = f >> 2, c = (f & 3) * 16;
            uint32_t d = base + FMK + (unsigned)(r * 64 + c);
            asm volatile("cp.async.cg.shared.global [%0], [%1], 16;"
                         :: "r"(d), "l"(ms + (long)r * SKV_ + c));
        }
        asm volatile("cp.async.commit_group;" ::: "memory");
    };

    auto computeS = [&](int buf, float (*sc)[4]) {
        uint32_t base = sbase + FST0 + (unsigned)buf * FSTRIDE;
#pragma unroll
        for (int j = 0; j < 8; j++)
#pragma unroll
            for (int e = 0; e < 4; e++) sc[j][e] = 0.0f;
#pragma unroll
        for (int kk = 0; kk < 4; kk++) {
            int kb = kk * 32 + hsel;
            uint32_t qaH[4], qaL[4];
            unsigned qoff = SWZ((unsigned)((wid * 16 + lr) * 128 + kb));
            ldm_x4(sbase + FQ_H + qoff, qaH);
            ldm_x4(sbase + FQ_L + qoff, qaL);
#pragma unroll
            for (int jj = 0; jj < 4; jj++) {
                unsigned boff = SWZ((unsigned)((jj * 16 + lr) * 128 + kb));
                uint32_t bH[4], bL[4];
                ldm_x4(base + FK_H + boff, bH);
                ldm_x4(base + FK_L + boff, bL);
#pragma unroll
                for (int t = 0; t < 2; t++) {
                    float* d = sc[jj * 2 + t];
                    mma_bf16(d, qaH, bH[t], bH[t + 2]);
                    mma_bf16(d, qaH, bL[t], bL[t + 2]);
                    mma_bf16(d, qaL, bH[t], bH[t + 2]);
                }
            }
        }
        // mask + scale
        const unsigned char* mk = (const unsigned char*)(smem + FST0 + (unsigned)buf * FSTRIDE + FMK);
#pragma unroll
        for (int j = 0; j < 8; j++) {
            int cl = j * 8 + ((lid & 3) << 1);
            float* d = sc[j];
            d[0] = mk[r0 * 64 + cl]           ? -1.0e9f : d[0] * 0.125f;
            d[1] = mk[r0 * 64 + cl + 1]       ? -1.0e9f : d[1] * 0.125f;
            d[2] = mk[(r0 + 8) * 64 + cl]     ? -1.0e9f : d[2] * 0.125f;
            d[3] = mk[(r0 + 8) * 64 + cl + 1] ? -1.0e9f : d[3] * 0.125f;
        }
    };

    // ---------------- pass 1: online stats ----------------
    float rm0 = -3.4e38f, rs0 = 0.0f, rm1 = -3.4e38f, rs1 = 0.0f;
    float sc[8][4];

    issue(0, false);
    for (int s = 0; s < 64; s++) {
        if (s + 1 < 64) {
            issue(s + 1, false);
            asm volatile("cp.async.wait_group 1;" ::: "memory");
        } else {
            asm volatile("cp.async.wait_group 0;" ::: "memory");
        }
        __syncthreads();
        computeS(s & 1, sc);

        float tm0 = -3.4e38f, tm1 = -3.4e38f;
#pragma unroll
        for (int j = 0; j < 8; j++) {
            tm0 = fmaxf(tm0, fmaxf(sc[j][0], sc[j][1]));
            tm1 = fmaxf(tm1, fmaxf(sc[j][2], sc[j][3]));
        }
        tm0 = fmaxf(tm0, __shfl_xor_sync(0xFFFFFFFFu, tm0, 1));
        tm0 = fmaxf(tm0, __shfl_xor_sync(0xFFFFFFFFu, tm0, 2));
        tm1 = fmaxf(tm1, __shfl_xor_sync(0xFFFFFFFFu, tm1, 1));
        tm1 = fmaxf(tm1, __shfl_xor_sync(0xFFFFFFFFu, tm1, 2));
        float m0n = fmaxf(rm0, tm0), m1n = fmaxf(rm1, tm1);
        float e0 = 0.0f, e1 = 0.0f;
#pragma unroll
        for (int j = 0; j < 8; j++) {
            e0 += __expf(sc[j][0] - m0n) + __expf(sc[j][1] - m0n);
            e1 += __expf(sc[j][2] - m1n) + __expf(sc[j][3] - m1n);
        }
        e0 += __shfl_xor_sync(0xFFFFFFFFu, e0, 1);
        e0 += __shfl_xor_sync(0xFFFFFFFFu, e0, 2);
        e1 += __shfl_xor_sync(0xFFFFFFFFu, e1, 1);
        e1 += __shfl_xor_sync(0xFFFFFFFFu, e1, 2);
        rs0 = rs0 * __expf(rm0 - m0n) + e0;  rm0 = m0n;
        rs1 = rs1 * __expf(rm1 - m1n) + e1;  rm1 = m1n;
        __syncthreads();
    }

    const float inv0 = 1.0f / rs0;
    const float inv1 = 1.0f / rs1;

    // ---------------- pass 2: recompute, normalize, write Wt, PV ----------------
    float dA[8][4];
#pragma unroll
    for (int j = 0; j < 8; j++)
#pragma unroll
        for (int e = 0; e < 4; e++) dA[j][e] = 0.0f;

    issue(0, true);
    for (int s = 0; s < 64; s++) {
        if (s + 1 < 64) {
            issue(s + 1, true);
            asm volatile("cp.async.wait_group 1;" ::: "memory");
        } else {
            asm volatile("cp.async.wait_group 0;" ::: "memory");
        }
        __syncthreads();
        computeS(s & 1, sc);

        uint32_t vbase = sbase + FST0 + (unsigned)(s & 1) * FSTRIDE;
        float* wrow = wtp + s * 64;
#pragma unroll
        for (int kk = 0; kk < 4; kk++) {
            const float* da = sc[2 * kk];
            const float* db = sc[2 * kk + 1];
            float wA0 = __expf(da[0] - rm0) * inv0;
            float wA1 = __expf(da[1] - rm0) * inv0;
            float wA2 = __expf(da[2] - rm1) * inv1;
            float wA3 = __expf(da[3] - rm1) * inv1;
            float wB0 = __expf(db[0] - rm0) * inv0;
            float wB1 = __expf(db[1] - rm0) * inv0;
            float wB2 = __expf(db[2] - rm1) * inv1;
            float wB3 = __expf(db[3] - rm1) * inv1;
            int clA = kk * 16 + ((lid & 3) << 1);
            *(float2*)(wrow + (long)r0 * SKV_ + clA)           = make_float2(wA0, wA1);
            *(float2*)(wrow + (long)(r0 + 8) * SKV_ + clA)     = make_float2(wA2, wA3);
            *(float2*)(wrow + (long)r0 * SKV_ + clA + 8)       = make_float2(wB0, wB1);
            *(float2*)(wrow + (long)(r0 + 8) * SKV_ + clA + 8) = make_float2(wB2, wB3);

            __nv_bfloat16 hA0 = __float2bfloat16(wA0), hA1 = __float2bfloat16(wA1);
            __nv_bfloat16 hA2 = __float2bfloat16(wA2), hA3 = __float2bfloat16(wA3);
            __nv_bfloat16 hB0 = __float2bfloat16(wB0), hB1 = __float2bfloat16(wB1);
            __nv_bfloat16 hB2 = __float2bfloat16(wB2), hB3 = __float2bfloat16(wB3);
            uint32_t ah[4], al[4];
            ah[0] = pk2(hA0, hA1); ah[1] = pk2(hA2, hA3);
            ah[2] = pk2(hB0, hB1); ah[3] = pk2(hB2, hB3);
            al[0] = pk2(__float2bfloat16(wA0 - __bfloat162float(hA0)),
                        __float2bfloat16(wA1 - __bfloat162float(hA1)));
            al[1] = pk2(__float2bfloat16(wA2 - __bfloat162float(hA2)),
                        __float2bfloat16(wA3 - __bfloat162float(hA3)));
            al[2] = pk2(__float2bfloat16(wB0 - __bfloat162float(hB0)),
                        __float2bfloat16(wB1 - __bfloat162float(hB1)));
            al[3] = pk2(__float2bfloat16(wB2 - __bfloat162float(hB2)),
                        __float2bfloat16(wB3 - __bfloat162float(hB3)));

            int kb = kk * 32 + hsel;
#pragma unroll
            for (int jj = 0; jj < 4; jj++) {
                unsigned voff = SWZ((unsigned)((jj * 16 + lr) * 128 + kb));
                uint32_t vH[4], vL[4];
                ldm_x4(vbase + FV_H + voff, vH);
                ldm_x4(vbase + FV_L + voff, vL);
#pragma unroll
                for (int t = 0; t < 2; t++) {
                    float* d = dA[jj * 2 + t];
                    mma_bf16(d, ah, vH[t], vH[t + 2]);
                    mma_bf16(d, ah, vL[t], vL[t + 2]);
                    mma_bf16(d, al, vH[t], vH[t + 2]);
                }
            }
        }
        __syncthreads();
    }

    // epilogue: write att pre-Wo as bf16 h/l
    __nv_bfloat16* aph = ath + ((long)b * SQ_ + m0) * DQ_ + h * DH_;
    __nv_bfloat16* apl = atl + ((long)b * SQ_ + m0) * DQ_ + h * DH_;
#pragma unroll
    for (int j = 0; j < 8; j++) {
        int cl = j * 8 + ((lid & 3) << 1);
        float v0 = dA[j][0], v1 = dA[j][1], v2 = dA[j][2], v3 = dA[j][3];
        __nv_bfloat16 h0 = __float2bfloat16(v0), h1 = __float2bfloat16(v1);
        __nv_bfloat16 h2 = __float2bfloat16(v2), h3 = __float2bfloat16(v3);
        *(uint32_t*)(aph + (long)r0 * DQ_ + cl)       = pk2(h0, h1);
        *(uint32_t*)(aph + (long)(r0 + 8) * DQ_ + cl) = pk2(h2, h3);
        *(uint32_t*)(apl + (long)r0 * DQ_ + cl) =
            pk2(__float2bfloat16(v0 - __bfloat162float(h0)),
                __float2bfloat16(v1 - __bfloat162float(h1)));
        *(uint32_t*)(apl + (long)(r0 + 8) * DQ_ + cl) =
            pk2(__float2bfloat16(v2 - __bfloat162float(h2)),
                __float2bfloat16(v3 - __bfloat162float(h3)));
    }
}

// ---------------------------------------------------------------------------
// bf16 transpose: v h/l [b][kv][ch] -> vt h/l [b][ch][kv]
// ---------------------------------------------------------------------------
__global__ __launch_bounds__(256)
void transpose_bf16_kernel(const __nv_bfloat16* __restrict__ vh,
                           const __nv_bfloat16* __restrict__ vl,
                           __nv_bfloat16* __restrict__ vth,
                           __nv_bfloat16* __restrict__ vtl)
{
    __shared__ __nv_bfloat16 th[32][34], tl[32][34];
    const int b   = blockIdx.z;
    const int kv0 = blockIdx.x * 32, ch0 = blockIdx.y * 32;
    const int x = threadIdx.x, y = threadIdx.y;
#pragma unroll
    for (int i = y; i < 32; i += 8) {
        long src = ((long)b * SKV_ + kv0 + i) * DQ_ + ch0 + x;
        th[i][x] = vh[src];
        tl[i][x] = vl[src];
    }
    __syncthreads();
#pragma unroll
    for (int i = y; i < 32; i += 8) {
        long dst = ((long)b * DQ_ + ch0 + i) * SKV_ + kv0 + x;
        vth[dst] = th[x][i];
        vtl[dst] = tl[x][i];
    }
}

// ---------------------------------------------------------------------------
// Launch
// ---------------------------------------------------------------------------
extern "C" void kernel_launch(void* const* d_in, const int* in_sizes, int n_in,
                              void* d_out, int out_size)
{
    (void)in_sizes; (void)n_in; (void)out_size;

    const float* Q   = (const float*)d_in[0];
    const float* K   = (const float*)d_in[1];
    const float* V   = (const float*)d_in[2];
    const void*  Msk = d_in[3];
    const float* Wq  = (const float*)d_in[4];
    const float* bq  = (const float*)d_in[5];
    const float* Wk  = (const float*)d_in[6];
    const float* bk  = (const float*)d_in[7];
    const float* Wv  = (const float*)d_in[8];
    const float* bv  = (const float*)d_in[9];
    const float* Wo  = (const float*)d_in[10];
    const float* bo  = (const float*)d_in[11];

    float* out = (float*)d_out;
    float* Wt  = out + (size_t)B_ * SQ_ * DOUT_;

    __nv_bfloat16 *sqh, *sql, *skh, *skl, *svh, *svl;
    __nv_bfloat16 *wqh, *wql, *wkh, *wkl, *wvh, *wvl, *woh, *wol;
    __nv_bfloat16 *qh, *ql, *kh, *kl, *vh, *vl, *vth, *vtl, *ath, *atl;
    unsigned char* mT;
    cudaGetSymbolAddress((void**)&sqh, g_sqh); cudaGetSymbolAddress((void**)&sql, g_sql);
    cudaGetSymbolAddress((void**)&skh, g_skh); cudaGetSymbolAddress((void**)&skl, g_skl);
    cudaGetSymbolAddress((void**)&svh, g_svh); cudaGetSymbolAddress((void**)&svl, g_svl);
    cudaGetSymbolAddress((void**)&wqh, g_wqh); cudaGetSymbolAddress((void**)&wql, g_wql);
    cudaGetSymbolAddress((void**)&wkh, g_wkh); cudaGetSymbolAddress((void**)&wkl, g_wkl);
    cudaGetSymbolAddress((void**)&wvh, g_wvh); cudaGetSymbolAddress((void**)&wvl, g_wvl);
    cudaGetSymbolAddress((void**)&woh, g_woh); cudaGetSymbolAddress((void**)&wol, g_wol);
    cudaGetSymbolAddress((void**)&qh,  g_qh);  cudaGetSymbolAddress((void**)&ql,  g_ql);
    cudaGetSymbolAddress((void**)&kh,  g_kh);  cudaGetSymbolAddress((void**)&kl,  g_kl);
    cudaGetSymbolAddress((void**)&vh,  g_vh);  cudaGetSymbolAddress((void**)&vl,  g_vl);
    cudaGetSymbolAddress((void**)&vth, g_vth); cudaGetSymbolAddress((void**)&vtl, g_vtl);
    cudaGetSymbolAddress((void**)&ath, g_ath); cudaGetSymbolAddress((void**)&atl, g_atl);
    cudaGetSymbolAddress((void**)&mT,  g_maskT);

    const int SMG = 2 * 49152;
    cudaFuncSetAttribute(hgemm_kernel<0>, cudaFuncAttributeMaxDynamicSharedMemorySize, SMG);
    cudaFuncSetAttribute(hgemm_kernel<3>, cudaFuncAttributeMaxDynamicSharedMemorySize, SMG);
    cudaFuncSetAttribute(fused_attn_kernel, cudaFuncAttributeMaxDynamicSharedMemorySize, FSMEM);

    // 0) probe + operand splits + mask transpose
    probe_mask_kernel<<<1, 1>>>((const unsigned int*)Msk);
    split_kernel<<<(B_ * SQ_ * DQ_)   / 1024, 256>>>(Q,  sqh, sql);
    split_kernel<<<(B_ * SKV_ * DKV_) / 1024, 256>>>(K, skh, skl);
    split_kernel<<<(B_ * SKV_ * DKV_) / 1024, 256>>>(V, svh, svl);
    split_kernel<<<(DQ_ * DQ_)   / 1024, 256>>>(Wq, wqh, wql);
    split_kernel<<<(DQ_ * DKV_)  / 1024, 256>>>(Wk, wkh, wkl);
    split_kernel<<<(DQ_ * DKV_)  / 1024, 256>>>(Wv, wvh, wvl);
    split_kernel<<<(DOUT_ * DQ_) / 1024, 256>>>(Wo, woh, wol);
    transpose_mask_kernel<<<dim3(SKV_ / 32, SQ_ / 32, B_), dim3(32, 8)>>>(Msk, mT);

    // 1) projections -> bf16 h/l
    hgemm_kernel<0><<<dim3(DQ_ / 64, (B_ * SQ_) / 128, 1), 256, SMG>>>(
        sqh, sql, DQ_, wqh, wql, DQ_, bq, qh, ql, DQ_, DQ_);
    hgemm_kernel<0><<<dim3(DQ_ / 64, (B_ * SKV_) / 128, 1), 256, SMG>>>(
        skh, skl, DKV_, wkh, wkl, DKV_, bk, kh, kl, DQ_, DKV_);
    hgemm_kernel<0><<<dim3(DQ_ / 64, (B_ * SKV_) / 128, 1), 256, SMG>>>(
        svh, svl, DKV_, wvh, wvl, DKV_, bv, vh, vl, DQ_, DKV_);

    // 1b) transpose projected V (bf16 h/l)
    transpose_bf16_kernel<<<dim3(SKV_ / 32, DQ_ / 32, B_), dim3(32, 8)>>>(
        vh, vl, vth, vtl);

    // 2) fused attention: scores + softmax + Wt write + PV
    fused_attn_kernel<<<dim3(SQ_ / 128, B_ * H_), 256, FSMEM>>>(
        qh, ql, kh, kl, vth, vtl, mT, Wt, ath, atl);

    // 3) output projection -> fp32 front of d_out
    hgemm_kernel<3><<<dim3(DOUT_ / 64, (B_ * SQ_) / 128, 1), 256, SMG>>>(
        ath, atl, DQ_, woh, wol, DQ_, bo, out, nullptr, DOUT_, DQ_);
}

// round 13
// speedup vs baseline: 1.1163x; 1.1163x over previous
#include <cuda_runtime.h>
#include <cuda_bf16.h>
#include <cstdint>
#include <math.h>

// Problem constants
#define B_    4
#define SQ_   1024
#define SKV_  4096
#define DQ_   1024
#define DKV_  768
#define H_    16
#define DH_   64
#define DOUT_ 256

#define SWZ(o) ((o) ^ (((o) >> 3) & 0x70))

// ---------------------------------------------------------------------------
// Scratch
// ---------------------------------------------------------------------------
#define AL16 __align__(16)
__device__ AL16 __nv_bfloat16 g_sqh[(size_t)B_ * SQ_  * DQ_ ], g_sql[(size_t)B_ * SQ_  * DQ_ ];
__device__ AL16 __nv_bfloat16 g_skh[(size_t)B_ * SKV_ * DKV_], g_skl[(size_t)B_ * SKV_ * DKV_];
__device__ AL16 __nv_bfloat16 g_svh[(size_t)B_ * SKV_ * DKV_], g_svl[(size_t)B_ * SKV_ * DKV_];
__device__ AL16 __nv_bfloat16 g_wqh[DQ_ * DQ_ ],  g_wql[DQ_ * DQ_ ];
__device__ AL16 __nv_bfloat16 g_wkh[DQ_ * DKV_],  g_wkl[DQ_ * DKV_];
__device__ AL16 __nv_bfloat16 g_wvh[DQ_ * DKV_],  g_wvl[DQ_ * DKV_];
__device__ AL16 __nv_bfloat16 g_woh[DOUT_ * DQ_], g_wol[DOUT_ * DQ_];
__device__ AL16 __nv_bfloat16 g_qh [(size_t)B_ * SQ_  * DQ_], g_ql [(size_t)B_ * SQ_  * DQ_];
__device__ AL16 __nv_bfloat16 g_kh [(size_t)B_ * SKV_ * DQ_], g_kl [(size_t)B_ * SKV_ * DQ_];
__device__ AL16 __nv_bfloat16 g_vth[(size_t)B_ * DQ_ * SKV_], g_vtl[(size_t)B_ * DQ_ * SKV_];
__device__ AL16 __nv_bfloat16 g_ath[(size_t)B_ * SQ_ * DQ_], g_atl[(size_t)B_ * SQ_ * DQ_];
__device__ AL16 unsigned char g_maskT[(size_t)B_ * SQ_ * SKV_];
#define NROWS_ (B_ * H_ * SQ_)
#define NTILES_ (SKV_ / 64)
__device__ AL16 float g_gmax[(size_t)NROWS_ * NTILES_];
__device__ AL16 float g_gsum[(size_t)NROWS_ * NTILES_];
__device__ AL16 float g_rowM[NROWS_];
__device__ AL16 float g_rowI[NROWS_];
__device__ int g_mask_flag;

// ---------------------------------------------------------------------------
// Mask dtype probe
// ---------------------------------------------------------------------------
__global__ void probe_mask_kernel(const unsigned int* __restrict__ m)
{
    if (blockIdx.x != 0 || threadIdx.x != 0) return;
    int is_i32 = 1, is_f32 = 1;
    for (int i = 0; i < 4096; i++) {
        unsigned v = m[i];
        if (v > 1u) is_i32 = 0;
        if (v != 0u && v != 0x3F800000u) is_f32 = 0;
    }
    g_mask_flag = is_i32 ? 1 : (is_f32 ? 2 : 0);
}

__device__ __forceinline__ bool read_mask(const void* m, long i, int flag)
{
    if (flag == 1) return ((const int*)m)[i] != 0;
    if (flag == 2) return ((const float*)m)[i] != 0.0f;
    return ((const unsigned char*)m)[i] != 0;
}

// ---------------------------------------------------------------------------
// Mask transpose: mask[b][kv][q] -> u8 maskT[b][q][kv]
// ---------------------------------------------------------------------------
__global__ __launch_bounds__(256)
void transpose_mask_kernel(const void* __restrict__ mask,
                           unsigned char* __restrict__ maskT)
{
    __shared__ unsigned char t[32][33];
    const int b   = blockIdx.z;
    const int kv0 = blockIdx.x * 32, q0 = blockIdx.y * 32;
    const int x = threadIdx.x, y = threadIdx.y;
    const int flag = g_mask_flag;
#pragma unroll
    for (int i = y; i < 32; i += 8)
        t[i][x] = read_mask(mask, ((long)b * SKV_ + kv0 + i) * SQ_ + q0 + x, flag) ? 1 : 0;
    __syncthreads();
#pragma unroll
    for (int i = y; i < 32; i += 8)
        maskT[((long)b * SQ_ + q0 + i) * SKV_ + kv0 + x] = t[x][i];
}

// ---------------------------------------------------------------------------
// Primitives
// ---------------------------------------------------------------------------
__device__ __forceinline__ uint32_t smem_to_u32(const void* p) {
    uint32_t a;
    asm("{ .reg .u64 t; cvta.to.shared.u64 t, %1; cvt.u32.u64 %0, t; }"
        : "=r"(a) : "l"(p));
    return a;
}

__device__ __forceinline__ void ldm_x4(uint32_t addr, uint32_t* r) {
    asm volatile("ldmatrix.sync.aligned.m8n8.x4.shared.b16 {%0,%1,%2,%3}, [%4];"
                 : "=r"(r[0]), "=r"(r[1]), "=r"(r[2]), "=r"(r[3]) : "r"(addr));
}

__device__ __forceinline__ void mma_bf16(float* d, const uint32_t* a,
                                         uint32_t b0, uint32_t b1) {
    asm volatile(
        "mma.sync.aligned.m16n8k16.row.col.f32.bf16.bf16.f32 "
        "{%0,%1,%2,%3}, {%4,%5,%6,%7}, {%8,%9}, {%0,%1,%2,%3};"
        : "+f"(d[0]), "+f"(d[1]), "+f"(d[2]), "+f"(d[3])
        : "r"(a[0]), "r"(a[1]), "r"(a[2]), "r"(a[3]), "r"(b0), "r"(b1));
}

__device__ __forceinline__ uint32_t pk2(__nv_bfloat16 a, __nv_bfloat16 b)
{
    return (uint32_t)__bfloat16_as_ushort(a) | ((uint32_t)__bfloat16_as_ushort(b) << 16);
}

__device__ __forceinline__ void cvt1(float4 v, char* hb, char* lb, int r, int cg)
{
    __nv_bfloat16 h0 = __float2bfloat16(v.x);
    __nv_bfloat16 h1 = __float2bfloat16(v.y);
    __nv_bfloat16 h2 = __float2bfloat16(v.z);
    __nv_bfloat16 h3 = __float2bfloat16(v.w);
    __nv_bfloat16 l0 = __float2bfloat16(v.x - __bfloat162float(h0));
    __nv_bfloat16 l1 = __float2bfloat16(v.y - __bfloat162float(h1));
    __nv_bfloat16 l2 = __float2bfloat16(v.z - __bfloat162float(h2));
    __nv_bfloat16 l3 = __float2bfloat16(v.w - __bfloat162float(h3));
    unsigned off = SWZ((unsigned)(r * 128 + (cg << 1)));
    *(uint2*)(hb + off) = make_uint2(pk2(h0, h1), pk2(h2, h3));
    *(uint2*)(lb + off) = make_uint2(pk2(l0, l1), pk2(l2, l3));
}

template<int ROWS>
__device__ __forceinline__ void cpa_tile(uint32_t dst, const __nv_bfloat16* src,
                                         int ld, int tid)
{
#pragma unroll
    for (int i = 0; i < ROWS / 32; i++) {
        int f = tid + i * 256;
        int r = f >> 3, c = f & 7;
        uint32_t d = dst + SWZ((unsigned)(r * 128 + c * 16));
        const void* s = src + (long)r * ld + c * 8;
        asm volatile("cp.async.cg.shared.global [%0], [%1], 16;" :: "r"(d), "l"(s));
    }
}

// ---------------------------------------------------------------------------
// Merged fp32 -> bf16 hi/lo split for all 7 operands (one launch)
// ---------------------------------------------------------------------------
__device__ __forceinline__ void split_body(const float* src,
                                           __nv_bfloat16* h, __nv_bfloat16* l,
                                           long blk, int tid)
{
    long i = (blk * 256 + tid) * 4;
    float4 v = *(const float4*)(src + i);
    __nv_bfloat16 h0 = __float2bfloat16(v.x), h1 = __float2bfloat16(v.y);
    __nv_bfloat16 h2 = __float2bfloat16(v.z), h3 = __float2bfloat16(v.w);
    *(uint2*)(h + i) = make_uint2(pk2(h0, h1), pk2(h2, h3));
    *(uint2*)(l + i) = make_uint2(
        pk2(__float2bfloat16(v.x - __bfloat162float(h0)),
            __float2bfloat16(v.y - __bfloat162float(h1))),
        pk2(__float2bfloat16(v.z - __bfloat162float(h2)),
            __float2bfloat16(v.w - __bfloat162float(h3))));
}

// block ranges: Q 4096 | K 12288 | V 12288 | Wq 1024 | Wk 768 | Wv 768 | Wo 256
__global__ __launch_bounds__(256)
void split_all_kernel(const float* __restrict__ Q, const float* __restrict__ K,
                      const float* __restrict__ V, const float* __restrict__ Wq,
                      const float* __restrict__ Wk, const float* __restrict__ Wv,
                      const float* __restrict__ Wo,
                      __nv_bfloat16* sqh, __nv_bfloat16* sql,
                      __nv_bfloat16* skh, __nv_bfloat16* skl,
                      __nv_bfloat16* svh, __nv_bfloat16* svl,
                      __nv_bfloat16* wqh, __nv_bfloat16* wql,
                      __nv_bfloat16* wkh, __nv_bfloat16* wkl,
                      __nv_bfloat16* wvh, __nv_bfloat16* wvl,
                      __nv_bfloat16* woh, __nv_bfloat16* wol)
{
    const int bx = blockIdx.x, tid = threadIdx.x;
    if      (bx < 4096)  split_body(Q,  sqh, sql, bx,          tid);
    else if (bx < 16384) split_body(K,  skh, skl, bx - 4096,   tid);
    else if (bx < 28672) split_body(V,  svh, svl, bx - 16384,  tid);
    else if (bx < 29696) split_body(Wq, wqh, wql, bx - 28672,  tid);
    else if (bx < 30464) split_body(Wk, wkh, wkl, bx - 29696,  tid);
    else if (bx < 31232) split_body(Wv, wvh, wvl, bx - 30464,  tid);
    else                 split_body(Wo, woh, wol, bx - 31232,  tid);
}

// ---------------------------------------------------------------------------
// Stats combine: per row, fold 64 tile (max, expsum) -> (M, 1/S)
// ---------------------------------------------------------------------------
__global__ __launch_bounds__(256)
void stats_combine_kernel(const float* __restrict__ gmax,
                          const float* __restrict__ gsum,
                          float* __restrict__ rowM, float* __restrict__ rowI)
{
    const int row  = blockIdx.x * 8 + (threadIdx.x >> 5);
    const int lane = threadIdx.x & 31;
    float m0 = gmax[(long)row * NTILES_ + lane];
    float m1 = gmax[(long)row * NTILES_ + lane + 32];
    float s0 = gsum[(long)row * NTILES_ + lane];
    float s1 = gsum[(long)row * NTILES_ + lane + 32];
    float M = fmaxf(m0, m1);
#pragma unroll
    for (int o = 16; o; o >>= 1) M = fmaxf(M, __shfl_xor_sync(0xFFFFFFFFu, M, o));
    float sc = s0 * __expf(m0 - M) + s1 * __expf(m1 - M);
#pragma unroll
    for (int o = 16; o; o >>= 1) sc += __shfl_xor_sync(0xFFFFFFFFu, sc, o);
    if (lane == 0) { rowM[row] = M; rowI[row] = 1.0f / sc; }
}

// ---------------------------------------------------------------------------
// bf16 hi/lo GEMM via HMMA.  D[128, 64] per CTA = A[128,K] @ B[64,K]^T
// MODE 0: projections (Q/K): +bias, write bf16 h/l
// MODE 1: scores per z=(b,h): mask+0.125, write fp32 Wt + tile stats
// MODE 2: PV per z=(b,h): A = fp32 Wt -> inline exp-normalize (writeback), B = vt h/l
// MODE 3: Wo: +bias, write fp32
// MODE 4: V-projection: +bias, write bf16 h/l TRANSPOSED to vt[b][ch][kv]
// ---------------------------------------------------------------------------
template<int MODE>
__global__ void __launch_bounds__(256, 2)
hgemm_kernel(const __nv_bfloat16* __restrict__ Ah, const __nv_bfloat16* __restrict__ Al,
             const float* __restrict__ Af, int lda,
             const __nv_bfloat16* __restrict__ Bh, const __nv_bfloat16* __restrict__ Bl, int ldb,
             const float* __restrict__ bias,
             void* __restrict__ C0, void* __restrict__ C1, int ldc, int Kdim,
             const unsigned char* __restrict__ maskT,
             float* __restrict__ gmax, float* __restrict__ gsum,
             const float* __restrict__ rowM, const float* __restrict__ rowI,
             float* __restrict__ Wtw)
{
    extern __shared__ char smem[];
    constexpr int NT = 64;
    constexpr int NF = NT / 16;                      // 4
    constexpr unsigned MASKSZ = (MODE == 1) ? 8192u : 0u;
    constexpr unsigned ABY = 128 * 128;
    constexpr unsigned BBY = NT * 128;
    constexpr unsigned BUFSZ = 2 * ABY + 2 * BBY;    // 49152

    const uint32_t sbase = smem_to_u32(smem);
    const int tid = threadIdx.x;
    const int wid = tid >> 5, lid = tid & 31;
    const int wm = wid & 3, wn = wid >> 2;           // 4(m) x 2(n)
    const int m0 = blockIdx.y * 128, n0 = blockIdx.x * NT, z = blockIdx.z;

    const __nv_bfloat16 *Aph = nullptr, *Apl = nullptr, *Bph, *Bpl;
    const float* Afp = nullptr;
    float* Wb = nullptr;
    int LDA, LDB, LDC = 0;
    char *Cp0 = nullptr, *Cp1 = nullptr;
    if (MODE == 0 || MODE == 3 || MODE == 4) {
        Aph = Ah + (long)m0 * lda;  Apl = Al + (long)m0 * lda;  LDA = lda;
        Bph = Bh + (long)n0 * ldb;  Bpl = Bl + (long)n0 * ldb;  LDB = ldb;
        LDC = ldc;
        long co = (long)m0 * ldc + n0;
        if (MODE == 0) { Cp0 = (char*)((__nv_bfloat16*)C0 + co); Cp1 = (char*)((__nv_bfloat16*)C1 + co); }
        else if (MODE == 3) { Cp0 = (char*)((float*)C0 + co); }
    } else if (MODE == 1) {
        int b = z >> 4, h = z & 15;
        long ao = ((long)b * SQ_  + m0) * DQ_ + h * DH_;
        long bo = ((long)b * SKV_ + n0) * DQ_ + h * DH_;
        Aph = Ah + ao; Apl = Al + ao; LDA = DQ_;
        Bph = Bh + bo; Bpl = Bl + bo; LDB = DQ_;
        LDC = SKV_;
        Cp0 = (char*)((float*)C0 + ((long)z * SQ_ + m0) * SKV_ + n0);
    } else {
        int b = z >> 4, h = z & 15;
        long wo = ((long)z * SQ_ + m0) * SKV_;
        Afp = Af + wo;  Wb = Wtw + wo;               LDA = SKV_;
        long bo = ((long)(b * DQ_ + h * DH_)) * SKV_;
        Bph = Bh + bo; Bpl = Bl + bo;                LDB = SKV_;
        LDC = DQ_;
        long co = ((long)b * SQ_ + m0) * DQ_ + h * DH_;
        Cp0 = (char*)((__nv_bfloat16*)C0 + co); Cp1 = (char*)((__nv_bfloat16*)C1 + co);
    }

    // MODE 1: stage mask tile [q 128][kv 64] into smem
    if (MODE == 1) {
        const unsigned char* msrc = maskT + ((long)(z >> 4) * SQ_ + m0) * SKV_ + n0;
#pragma unroll
        for (int it = 0; it < 8; it++) {
            int idx = it * 1024 + tid * 4;
            int r = idx >> 6, c = idx & 63;
            *(uint32_t*)(smem + idx) = *(const uint32_t*)(msrc + (long)r * SKV_ + c);
        }
    }

    // MODE 2: per-thread row stats
    float sM[MODE == 2 ? 8 : 1], sI[MODE == 2 ? 8 : 1];
    if (MODE == 2) {
        long rb = (long)z * SQ_ + m0;
#pragma unroll
        for (int i = 0; i < 8; i++) {
            int r = (tid >> 4) + i * 16;
            sM[i] = rowM[rb + r];
            sI[i] = rowI[rb + r];
        }
    }

    float dc[2 * NF][4];
#pragma unroll
    for (int i = 0; i < 2 * NF; i++)
#pragma unroll
        for (int j = 0; j < 4; j++) dc[i][j] = 0.0f;

    float4 stg[MODE == 2 ? 8 : 1];

    const int ns = Kdim >> 6;

    auto issueB = [&](int s) {
        uint32_t base = sbase + MASKSZ + (unsigned)(s & 1) * BUFSZ;
        cpa_tile<NT>(base + 2 * ABY,       Bph + (long)s * 64, LDB, tid);
        cpa_tile<NT>(base + 2 * ABY + BBY, Bpl + (long)s * 64, LDB, tid);
    };
    auto issueA = [&](int s) {
        uint32_t base = sbase + MASKSZ + (unsigned)(s & 1) * BUFSZ;
        cpa_tile<128>(base,       Aph + (long)s * 64, LDA, tid);
        cpa_tile<128>(base + ABY, Apl + (long)s * 64, LDA, tid);
    };
    auto ldgA = [&](int s) {
        const float* As = Afp + s * 64;
#pragma unroll
        for (int i = 0; i < 8; i++) {
            int f = tid + i * 256, r = f >> 4, cg = (f & 15) << 2;
            stg[i] = *(const float4*)(As + (long)r * LDA + cg);
        }
    };
    auto cvtstsA = [&](int s) {
        char* ah = smem + (size_t)(s & 1) * BUFSZ;
        char* al = ah + ABY;
        float* wb = Wb + s * 64;
#pragma unroll
        for (int i = 0; i < 8; i++) {
            int f = tid + i * 256, r = f >> 4, cg = (f & 15) << 2;
            float4 v = stg[i];
            float4 w;
            w.x = __expf(v.x - sM[i]) * sI[i];
            w.y = __expf(v.y - sM[i]) * sI[i];
            w.z = __expf(v.z - sM[i]) * sI[i];
            w.w = __expf(v.w - sM[i]) * sI[i];
            *(float4*)(wb + (long)r * LDA + cg) = w;
            cvt1(w, ah, al, r, cg);
        }
    };

    auto compute = [&](int buf) {
        const uint32_t sA  = sbase + MASKSZ + (unsigned)buf * BUFSZ;
        const uint32_t sAl = sA + ABY;
        const uint32_t sB  = sA + 2 * ABY;
        const uint32_t sBl = sB + BBY;
        const int lr = lid & 15, hsel = (lid >> 4) << 4;
#pragma unroll
        for (int ks = 0; ks < 4; ks++) {
            const int kb = ks * 32 + hsel;
            uint32_t aH[2][4], aL[2][4];
#pragma unroll
            for (int i = 0; i < 2; i++) {
                unsigned off = SWZ((unsigned)((wm * 32 + i * 16 + lr) * 128 + kb));
                ldm_x4(sA + off, aH[i]);
                ldm_x4(sAl + off, aL[i]);
            }
#pragma unroll
            for (int jj = 0; jj < NF / 2; jj++) {
                unsigned off = SWZ((unsigned)((wn * (NT / 2) + jj * 16 + lr) * 128 + kb));
                uint32_t bH[4], bL[4];
                ldm_x4(sB + off, bH);
                ldm_x4(sBl + off, bL);
#pragma unroll
                for (int i = 0; i < 2; i++) {
#pragma unroll
                    for (int t = 0; t < 2; t++) {
                        float* d = dc[i * NF + jj * 2 + t];
                        mma_bf16(d, aH[i], bH[t], bH[t + 2]);
                        mma_bf16(d, aH[i], bL[t], bL[t + 2]);
                        mma_bf16(d, aL[i], bH[t], bH[t + 2]);
                    }
                }
            }
        }
    };

    if (MODE == 2) {
        ldgA(0);
        issueB(0);
        asm volatile("cp.async.commit_group;" ::: "memory");
        cvtstsA(0);
        for (int s = 0; s < ns; s++) {
            if (s + 1 < ns) {
                ldgA(s + 1);
                issueB(s + 1);
                asm volatile("cp.async.commit_group;" ::: "memory");
                asm volatile("cp.async.wait_group 1;" ::: "memory");
            } else {
                asm volatile("cp.async.wait_group 0;" ::: "memory");
            }
            __syncthreads();
            compute(s & 1);
            if (s + 1 < ns) cvtstsA(s + 1);
            __syncthreads();
        }
    } else {
        issueA(0); issueB(0);
        asm volatile("cp.async.commit_group;" ::: "memory");
        for (int s = 0; s < ns; s++) {
            if (s + 1 < ns) {
                issueA(s + 1); issueB(s + 1);
                asm volatile("cp.async.commit_group;" ::: "memory");
                asm volatile("cp.async.wait_group 1;" ::: "memory");
            } else {
                asm volatile("cp.async.wait_group 0;" ::: "memory");
            }
            __syncthreads();
            compute(s & 1);
            __syncthreads();
        }
    }

    // ---- epilogue ----
    if (MODE == 1) {
        const unsigned char* mk = (const unsigned char*)smem;
        float* pm = (float*)(smem + MASKSZ);         // [2][128]
        float* ps = pm + 256;                        // [2][128]
        float* cm = ps + 256;                        // [128]
        float* cp = (float*)Cp0;
        float rmax[2][2];
#pragma unroll
        for (int i = 0; i < 2; i++) {
            rmax[i][0] = -3.4e38f; rmax[i][1] = -3.4e38f;
            int rl = wm * 32 + i * 16 + (lid >> 2);
#pragma unroll
            for (int f = 0; f < NF; f++) {
                int cl = wn * (NT / 2) + f * 8 + ((lid & 3) << 1);
                float* d = dc[i * NF + f];
                d[0] = mk[rl * 64 + cl]           ? -1.0e9f : d[0] * 0.125f;
                d[1] = mk[rl * 64 + cl + 1]       ? -1.0e9f : d[1] * 0.125f;
                d[2] = mk[(rl + 8) * 64 + cl]     ? -1.0e9f : d[2] * 0.125f;
                d[3] = mk[(rl + 8) * 64 + cl + 1] ? -1.0e9f : d[3] * 0.125f;
                rmax[i][0] = fmaxf(rmax[i][0], fmaxf(d[0], d[1]));
                rmax[i][1] = fmaxf(rmax[i][1], fmaxf(d[2], d[3]));
                *(float2*)(cp + (long)rl * LDC + cl)       = make_float2(d[0], d[1]);
                *(float2*)(cp + (long)(rl + 8) * LDC + cl) = make_float2(d[2], d[3]);
            }
        }
#pragma unroll
        for (int i = 0; i < 2; i++)
#pragma unroll
            for (int s = 0; s < 2; s++) {
                float m = rmax[i][s];
                m = fmaxf(m, __shfl_xor_sync(0xFFFFFFFFu, m, 1));
                m = fmaxf(m, __shfl_xor_sync(0xFFFFFFFFu, m, 2));
                rmax[i][s] = m;
            }
        if ((lid & 3) == 0) {
#pragma unroll
            for (int i = 0; i < 2; i++)
#pragma unroll
                for (int s = 0; s < 2; s++)
                    pm[wn * 128 + wm * 32 + i * 16 + (lid >> 2) + s * 8] = rmax[i][s];
        }
        __syncthreads();
        if (tid < 128) cm[tid] = fmaxf(pm[tid], pm[128 + tid]);
        __syncthreads();
        float rsum[2][2] = {{0.0f, 0.0f}, {0.0f, 0.0f}};
#pragma unroll
        for (int i = 0; i < 2; i++) {
            int rl = wm * 32 + i * 16 + (lid >> 2);
            float mv0 = cm[rl], mv1 = cm[rl + 8];
#pragma unroll
            for (int f = 0; f < NF; f++) {
                float* d = dc[i * NF + f];
                rsum[i][0] += __expf(d[0] - mv0) + __expf(d[1] - mv0);
                rsum[i][1] += __expf(d[2] - mv1) + __expf(d[3] - mv1);
            }
        }
#pragma unroll
        for (int i = 0; i < 2; i++)
#pragma unroll
            for (int s = 0; s < 2; s++) {
                float v = rsum[i][s];
                v += __shfl_xor_sync(0xFFFFFFFFu, v, 1);
                v += __shfl_xor_sync(0xFFFFFFFFu, v, 2);
                rsum[i][s] = v;
            }
        if ((lid & 3) == 0) {
#pragma unroll
            for (int i = 0; i < 2; i++)
#pragma unroll
                for (int s = 0; s < 2; s++)
                    ps[wn * 128 + wm * 32 + i * 16 + (lid >> 2) + s * 8] = rsum[i][s];
        }
        __syncthreads();
        if (tid < 128) {
            long rg = (long)z * SQ_ + m0 + tid;
            gmax[rg * NTILES_ + blockIdx.x] = cm[tid];
            gsum[rg * NTILES_ + blockIdx.x] = ps[tid] + ps[128 + tid];
        }
        return;
    }

    if (MODE == 4) {
        // stage [ch 64][kv 128] fp32 (pad 129), then write transposed bf16 h/l
        float* st = (float*)smem;                    // 64*129*4 = 33024 B
#pragma unroll
        for (int i = 0; i < 2; i++) {
#pragma unroll
            for (int f = 0; f < NF; f++) {
                const float* d = dc[i * NF + f];
                int rl = wm * 32 + i * 16 + (lid >> 2);
                int cl = wn * (NT / 2) + f * 8 + ((lid & 3) << 1);
                float2 bb = *(const float2*)(bias + n0 + cl);
                st[(cl + 0) * 129 + rl]     = d[0] + bb.x;
                st[(cl + 1) * 129 + rl]     = d[1] + bb.y;
                st[(cl + 0) * 129 + rl + 8] = d[2] + bb.x;
                st[(cl + 1) * 129 + rl + 8] = d[3] + bb.y;
            }
        }
        __syncthreads();
        const int b = m0 >> 12, kv0 = m0 & 4095;
        __nv_bfloat16* vth = (__nv_bfloat16*)C0;
        __nv_bfloat16* vtl = (__nv_bfloat16*)C1;
        for (int e = tid; e < 64 * 32; e += 256) {
            int ch = e >> 5, kvg = (e & 31) * 4;
            const float* sr = st + ch * 129 + kvg;
            float v0 = sr[0], v1 = sr[1], v2 = sr[2], v3 = sr[3];
            __nv_bfloat16 h0 = __float2bfloat16(v0), h1 = __float2bfloat16(v1);
            __nv_bfloat16 h2 = __float2bfloat16(v2), h3 = __float2bfloat16(v3);
            long dst = ((long)(b * DQ_ + n0 + ch)) * SKV_ + kv0 + kvg;
            *(uint2*)(vth + dst) = make_uint2(pk2(h0, h1), pk2(h2, h3));
            *(uint2*)(vtl + dst) = make_uint2(
                pk2(__float2bfloat16(v0 - __bfloat162float(h0)),
                    __float2bfloat16(v1 - __bfloat162float(h1))),
                pk2(__float2bfloat16(v2 - __bfloat162float(h2)),
                    __float2bfloat16(v3 - __bfloat162float(h3))));
        }
        return;
    }

#pragma unroll
    for (int i = 0; i < 2; i++) {
#pragma unroll
        for (int f = 0; f < NF; f++) {
            const float* d = dc[i * NF + f];
            int rl = wm * 32 + i * 16 + (lid >> 2);
            int cl = wn * (NT / 2) + f * 8 + ((lid & 3) << 1);
            if (MODE == 0 || MODE == 2) {
                float bx = 0.0f, by = 0.0f;
                if (MODE == 0) { float2 bb = *(const float2*)(bias + n0 + cl); bx = bb.x; by = bb.y; }
                float v0 = d[0] + bx, v1 = d[1] + by;
                float v2 = d[2] + bx, v3 = d[3] + by;
                __nv_bfloat16 h0 = __float2bfloat16(v0), h1 = __float2bfloat16(v1);
                __nv_bfloat16 h2 = __float2bfloat16(v2), h3 = __float2bfloat16(v3);
                __nv_bfloat16* ch = (__nv_bfloat16*)Cp0;
                __nv_bfloat16* cll = (__nv_bfloat16*)Cp1;
                *(uint32_t*)(ch + (long)rl * LDC + cl)       = pk2(h0, h1);
                *(uint32_t*)(ch + (long)(rl + 8) * LDC + cl) = pk2(h2, h3);
                *(uint32_t*)(cll + (long)rl * LDC + cl) =
                    pk2(__float2bfloat16(v0 - __bfloat162float(h0)),
                        __float2bfloat16(v1 - __bfloat162float(h1)));
                *(uint32_t*)(cll + (long)(rl + 8) * LDC + cl) =
                    pk2(__float2bfloat16(v2 - __bfloat162float(h2)),
                        __float2bfloat16(v3 - __bfloat162float(h3)));
            } else {
                float2 bb = *(const float2*)(bias + n0 + cl);
                float* cp = (float*)Cp0;
                *(float2*)(cp + (long)rl * LDC + cl) =
                    make_float2(d[0] + bb.x, d[1] + bb.y);
                *(float2*)(cp + (long)(rl + 8) * LDC + cl) =
                    make_float2(d[2] + bb.x, d[3] + bb.y);
            }
        }
    }
}

// ---------------------------------------------------------------------------
// Launch
// ---------------------------------------------------------------------------
extern "C" void kernel_launch(void* const* d_in, const int* in_sizes, int n_in,
                              void* d_out, int out_size)
{
    (void)in_sizes; (void)n_in; (void)out_size;

    const float* Q   = (const float*)d_in[0];
    const float* K   = (const float*)d_in[1];
    const float* V   = (const float*)d_in[2];
    const void*  Msk = d_in[3];
    const float* Wq  = (const float*)d_in[4];
    const float* bq  = (const float*)d_in[5];
    const float* Wk  = (const float*)d_in[6];
    const float* bk  = (const float*)d_in[7];
    const float* Wv  = (const float*)d_in[8];
    const float* bv  = (const float*)d_in[9];
    const float* Wo  = (const float*)d_in[10];
    const float* bo  = (const float*)d_in[11];

    float* out = (float*)d_out;
    float* Wt  = out + (size_t)B_ * SQ_ * DOUT_;

    __nv_bfloat16 *sqh, *sql, *skh, *skl, *svh, *svl;
    __nv_bfloat16 *wqh, *wql, *wkh, *wkl, *wvh, *wvl, *woh, *wol;
    __nv_bfloat16 *qh, *ql, *kh, *kl, *vth, *vtl, *ath, *atl;
    unsigned char* mT;
    float *gmx, *gsm, *rM, *rI;
    cudaGetSymbolAddress((void**)&sqh, g_sqh); cudaGetSymbolAddress((void**)&sql, g_sql);
    cudaGetSymbolAddress((void**)&skh, g_skh); cudaGetSymbolAddress((void**)&skl, g_skl);
    cudaGetSymbolAddress((void**)&svh, g_svh); cudaGetSymbolAddress((void**)&svl, g_svl);
    cudaGetSymbolAddress((void**)&wqh, g_wqh); cudaGetSymbolAddress((void**)&wql, g_wql);
    cudaGetSymbolAddress((void**)&wkh, g_wkh); cudaGetSymbolAddress((void**)&wkl, g_wkl);
    cudaGetSymbolAddress((void**)&wvh, g_wvh); cudaGetSymbolAddress((void**)&wvl, g_wvl);
    cudaGetSymbolAddress((void**)&woh, g_woh); cudaGetSymbolAddress((void**)&wol, g_wol);
    cudaGetSymbolAddress((void**)&qh,  g_qh);  cudaGetSymbolAddress((void**)&ql,  g_ql);
    cudaGetSymbolAddress((void**)&kh,  g_kh);  cudaGetSymbolAddress((void**)&kl,  g_kl);
    cudaGetSymbolAddress((void**)&vth, g_vth); cudaGetSymbolAddress((void**)&vtl, g_vtl);
    cudaGetSymbolAddress((void**)&ath, g_ath); cudaGetSymbolAddress((void**)&atl, g_atl);
    cudaGetSymbolAddress((void**)&mT,  g_maskT);
    cudaGetSymbolAddress((void**)&gmx, g_gmax); cudaGetSymbolAddress((void**)&gsm, g_gsum);
    cudaGetSymbolAddress((void**)&rM,  g_rowM); cudaGetSymbolAddress((void**)&rI,  g_rowI);

    const int SMG = 2 * 49152;            // 98304: modes 0,2,3,4 (2 CTAs/SM)
    const int SM1 = 8192 + 49152;         // 57344: mode 1
    cudaFuncSetAttribute(hgemm_kernel<0>, cudaFuncAttributeMaxDynamicSharedMemorySize, SMG);
    cudaFuncSetAttribute(hgemm_kernel<1>, cudaFuncAttributeMaxDynamicSharedMemorySize, SM1);
    cudaFuncSetAttribute(hgemm_kernel<2>, cudaFuncAttributeMaxDynamicSharedMemorySize, SMG);
    cudaFuncSetAttribute(hgemm_kernel<3>, cudaFuncAttributeMaxDynamicSharedMemorySize, SMG);
    cudaFuncSetAttribute(hgemm_kernel<4>, cudaFuncAttributeMaxDynamicSharedMemorySize, SMG);

    // 0) probe + merged operand splits + mask transpose
    probe_mask_kernel<<<1, 1>>>((const unsigned int*)Msk);
    split_all_kernel<<<31488, 256>>>(Q, K, V, Wq, Wk, Wv, Wo,
                                     sqh, sql, skh, skl, svh, svl,
                                     wqh, wql, wkh, wkl, wvh, wvl, woh, wol);
    transpose_mask_kernel<<<dim3(SKV_ / 32, SQ_ / 32, B_), dim3(32, 8)>>>(Msk, mT);

    // 1) projections: Q,K -> bf16 h/l; V -> transposed vt bf16 h/l
    hgemm_kernel<0><<<dim3(DQ_ / 64, (B_ * SQ_) / 128, 1), 256, SMG>>>(
        sqh, sql, nullptr, DQ_, wqh, wql, DQ_, bq, qh, ql, DQ_, DQ_,
        nullptr, nullptr, nullptr, nullptr, nullptr, nullptr);
    hgemm_kernel<0><<<dim3(DQ_ / 64, (B_ * SKV_) / 128, 1), 256, SMG>>>(
        skh, skl, nullptr, DKV_, wkh, wkl, DKV_, bk, kh, kl, DQ_, DKV_,
        nullptr, nullptr, nullptr, nullptr, nullptr, nullptr);
    hgemm_kernel<4><<<dim3(DQ_ / 64, (B_ * SKV_) / 128, 1), 256, SMG>>>(
        svh, svl, nullptr, DKV_, wvh, wvl, DKV_, bv, vth, vtl, 0, DKV_,
        nullptr, nullptr, nullptr, nullptr, nullptr, nullptr);

    // 2) masked scores -> fp32 Wt + per-tile softmax stats
    hgemm_kernel<1><<<dim3(SKV_ / 64, SQ_ / 128, B_ * H_), 256, SM1>>>(
        qh, ql, nullptr, 0, kh, kl, 0, nullptr, Wt, nullptr, 0, DH_,
        mT, gmx, gsm, nullptr, nullptr, nullptr);

    // 3) fold tile stats -> per-row (M, 1/S)
    stats_combine_kernel<<<NROWS_ / 8, 256>>>(gmx, gsm, rM, rI);

    // 4) PV: exp-normalize Wt inline (writeback normalized weights), GEMM with V^T
    hgemm_kernel<2><<<dim3(1, SQ_ / 128, B_ * H_), 256, SMG>>>(
        nullptr, nullptr, Wt, 0, vth, vtl, 0, nullptr, ath, atl, 0, SKV_,
        nullptr, nullptr, nullptr, rM, rI, Wt);

    // 5) output projection -> fp32 front of d_out
    hgemm_kernel<3><<<dim3(DOUT_ / 64, (B_ * SQ_) / 128, 1), 256, SMG>>>(
        ath, atl, nullptr, DQ_, woh, wol, DQ_, bo, out, nullptr, DOUT_, DQ_,
        nullptr, nullptr, nullptr, nullptr, nullptr, nullptr);
}